// round 6
// baseline (speedup 1.0000x reference)
#include <cuda_runtime.h>
#include <math.h>
#include <stdint.h>

#define BB 8
#define TT 2048
#define CC 1024
#define HH 128

__device__ float g_q[BB * TT * HH];
__device__ float g_k[BB * TT * HH];
__device__ float g_vt[BB * HH * TT];   // V transposed: [b][h][t]

// ---------------------------------------------------------------------------
// PTX helpers
// ---------------------------------------------------------------------------
__device__ __forceinline__ void mma_tf32(float c[4], const uint32_t a[4],
                                         uint32_t b0, uint32_t b1) {
    asm volatile(
        "mma.sync.aligned.m16n8k8.row.col.f32.tf32.tf32.f32 "
        "{%0,%1,%2,%3}, {%4,%5,%6,%7}, {%8,%9}, {%0,%1,%2,%3};"
        : "+f"(c[0]), "+f"(c[1]), "+f"(c[2]), "+f"(c[3])
        : "r"(a[0]), "r"(a[1]), "r"(a[2]), "r"(a[3]), "r"(b0), "r"(b1));
}

__device__ __forceinline__ void ldsm_x4(uint32_t r[4], uint32_t addr) {
    asm volatile("ldmatrix.sync.aligned.m8n8.x4.shared.b16 {%0,%1,%2,%3}, [%4];"
        : "=r"(r[0]), "=r"(r[1]), "=r"(r[2]), "=r"(r[3]) : "r"(addr));
}

__device__ __forceinline__ uint32_t f2tf(float f) {
    uint32_t u;
    asm("cvt.rna.tf32.f32 %0, %1;" : "=r"(u) : "f"(f));
    return u;
}
__device__ __forceinline__ float f2tff(float f) { return __uint_as_float(f2tf(f)); }

__device__ __forceinline__ uint32_t smem_u32(const void* p) {
    uint32_t a;
    asm("{ .reg .u64 t; cvta.to.shared.u64 t, %1; cvt.u32.u64 %0, t; }" : "=r"(a) : "l"(p));
    return a;
}

#define CP_ASYNC16(dst, src) \
    asm volatile("cp.async.cg.shared.global [%0], [%1], 16;" :: "r"(dst), "l"(src) : "memory")
#define CP_COMMIT() asm volatile("cp.async.commit_group;" ::: "memory")
#define CP_WAIT0()  asm volatile("cp.async.wait_group 0;" ::: "memory")
#define CP_WAIT1()  asm volatile("cp.async.wait_group 1;" ::: "memory")

// ===========================================================================
// Kernel 1: QKV projection, tf32 mma.sync + ldmatrix, occupancy 2.
// out[r][h] = sum_c x[r][c] * W[h][c].  M=16384, N=128, K=1024.
// BM=128, BN=128, BK=32. 256 threads = 8 warps (4 M x 2 N), warp tile 32x64.
// mat 0 -> g_q, mat 1 -> g_k, mat 2 -> g_vt (transposed store).
// ===========================================================================
#define QKV_AS 4608              // 128*36 floats
#define QKV_SMEM_BYTES (4 * QKV_AS * 4)

__global__ __launch_bounds__(256, 2) void qkv_mma_kernel(
    const float* __restrict__ x,
    const float* __restrict__ Wq,
    const float* __restrict__ Wk,
    const float* __restrict__ Wv)
{
    extern __shared__ float sm[];
    const uint32_t sb = smem_u32(sm);
    const int mat = blockIdx.y;
    const float* W = (mat == 0) ? Wq : (mat == 1) ? Wk : Wv;

    const int tid = threadIdx.x;
    const int lid = tid & 31;
    const int wid = tid >> 5;
    const int g = lid >> 2;
    const int c = lid & 3;
    const int wm = wid & 3;       // M group (32 rows)
    const int wn = wid >> 2;      // N group (64 cols)
    const int m0 = blockIdx.x * 128;

    // ldmatrix lane offsets (bytes); row stride = 36 floats = 144 B (16B-aligned)
    const uint32_t a_l_off = ((((lid >> 3) & 1) * 8 + (lid & 7)) * 144) + ((lid >> 4) * 16);
    const uint32_t b_l_off = ((lid & 7) * 144) + ((lid >> 3) * 16);

    float acc[2][8][4];
    #pragma unroll
    for (int mi = 0; mi < 2; mi++)
        #pragma unroll
        for (int ni = 0; ni < 8; ni++)
            #pragma unroll
            for (int j = 0; j < 4; j++) acc[mi][ni][j] = 0.0f;

    float4 xr[4], wr[4];

    auto loadT = [&](int it) {
        const int k0 = it * 32;
        #pragma unroll
        for (int j = 0; j < 4; j++) {
            int idx = tid + j * 256;
            int m = idx >> 3;
            int kq = (idx & 7) << 2;
            xr[j] = *reinterpret_cast<const float4*>(&x[(size_t)(m0 + m) * CC + k0 + kq]);
            wr[j] = *reinterpret_cast<const float4*>(&W[(size_t)m * CC + k0 + kq]);
        }
    };
    auto stsT = [&](int p) {
        float* As = sm + p * QKV_AS;
        float* Bs = sm + 2 * QKV_AS + p * QKV_AS;
        #pragma unroll
        for (int j = 0; j < 4; j++) {
            int idx = tid + j * 256;
            int m = idx >> 3;
            int kq = (idx & 7) << 2;
            uint4 ua = make_uint4(f2tf(xr[j].x), f2tf(xr[j].y), f2tf(xr[j].z), f2tf(xr[j].w));
            uint4 ub = make_uint4(f2tf(wr[j].x), f2tf(wr[j].y), f2tf(wr[j].z), f2tf(wr[j].w));
            *reinterpret_cast<uint4*>(&As[m * 36 + kq]) = ua;
            *reinterpret_cast<uint4*>(&Bs[m * 36 + kq]) = ub;
        }
    };

    loadT(0);
    stsT(0);
    __syncthreads();

    for (int it = 0; it < 32; ++it) {
        const int p = it & 1;
        if (it < 31) loadT(it + 1);

        const uint32_t aaddr0 = sb + p * (QKV_AS * 4) + wm * (32 * 144) + a_l_off;
        const uint32_t aaddr1 = aaddr0 + 16 * 144;
        const uint32_t baddr  = sb + (2 + p) * (QKV_AS * 4) + wn * (64 * 144) + b_l_off;

        #pragma unroll
        for (int kp = 0; kp < 2; kp++) {
            uint32_t a0[4], a1[4], a0b[4], a1b[4];
            ldsm_x4(a0,  aaddr0 + kp * 64);
            ldsm_x4(a1,  aaddr1 + kp * 64);
            ldsm_x4(a0b, aaddr0 + kp * 64 + 32);
            ldsm_x4(a1b, aaddr1 + kp * 64 + 32);
            #pragma unroll
            for (int ni = 0; ni < 8; ni++) {
                uint32_t b4[4];
                ldsm_x4(b4, baddr + ni * (8 * 144) + kp * 64);
                mma_tf32(acc[0][ni], a0,  b4[0], b4[1]);
                mma_tf32(acc[1][ni], a1,  b4[0], b4[1]);
                mma_tf32(acc[0][ni], a0b, b4[2], b4[3]);
                mma_tf32(acc[1][ni], a1b, b4[2], b4[3]);
            }
        }

        if (it < 31) stsT(p ^ 1);
        __syncthreads();
    }

    // Epilogue: round to tf32 so attention operands are exact tf32.
    if (mat < 2) {
        float* out = (mat == 0) ? g_q : g_k;
        #pragma unroll
        for (int mi = 0; mi < 2; mi++) {
            int row0 = m0 + wm * 32 + mi * 16 + g;
            int row1 = row0 + 8;
            #pragma unroll
            for (int ni = 0; ni < 8; ni++) {
                int col = wn * 64 + ni * 8 + 2 * c;
                float2 v0 = make_float2(f2tff(acc[mi][ni][0]), f2tff(acc[mi][ni][1]));
                float2 v1 = make_float2(f2tff(acc[mi][ni][2]), f2tff(acc[mi][ni][3]));
                *reinterpret_cast<float2*>(&out[(size_t)row0 * HH + col]) = v0;
                *reinterpret_cast<float2*>(&out[(size_t)row1 * HH + col]) = v1;
            }
        }
    } else {
        // V: store transposed -> g_vt[b][h][t]
        float* vtb = g_vt + (size_t)(m0 / TT) * HH * TT;
        const int tbase = m0 % TT;
        #pragma unroll
        for (int mi = 0; mi < 2; mi++) {
            int t0 = tbase + wm * 32 + mi * 16 + g;
            int t1 = t0 + 8;
            #pragma unroll
            for (int ni = 0; ni < 8; ni++) {
                int col = wn * 64 + ni * 8 + 2 * c;
                vtb[(size_t)col * TT + t0]       = f2tff(acc[mi][ni][0]);
                vtb[(size_t)(col + 1) * TT + t0] = f2tff(acc[mi][ni][1]);
                vtb[(size_t)col * TT + t1]       = f2tff(acc[mi][ni][2]);
                vtb[(size_t)(col + 1) * TT + t1] = f2tff(acc[mi][ni][3]);
            }
        }
    }
}

// ===========================================================================
// Kernel 2: causal flash attention, tf32 mma.sync, all-ldmatrix, occ 2.
// BQ=BKV=64, 128 threads (4 warps), warp = 16 q-rows x 128 cols.
// Smem: Q 64x128 (swz, loaded once), K 64x128 (swz, single buf),
//       VT 128x64 (swz), P 64x64 (swz).  Total 112 KB -> 2 CTAs/SM.
// ===========================================================================
#define AQ  0            // floats
#define AK  8192
#define AVT 16384
#define AP  24576
#define ATT_SMEM_FLOATS (24576 + 64 * 64)
#define ATT_SMEM_BYTES (ATT_SMEM_FLOATS * 4)   // 114,688 B

__global__ __launch_bounds__(128, 2) void attn_mma_kernel(float* __restrict__ out)
{
    extern __shared__ float sm[];
    const uint32_t sb = smem_u32(sm);

    const int b  = blockIdx.y;
    const int qt = (gridDim.x - 1) - blockIdx.x;   // heavy tiles first
    const int q0 = qt * 64;
    const int tid = threadIdx.x;
    const int wid = tid >> 5;
    const int lid = tid & 31;
    const int g = lid >> 2;
    const int c = lid & 3;
    const int r0w = wid * 16;

    const float* qg  = g_q  + (size_t)b * TT * HH;
    const float* kg  = g_k  + (size_t)b * TT * HH;
    const float* vtg = g_vt + (size_t)b * HH * TT;

    // 64x128 tile (Q/K): row r, 16B chunk kc -> chunk kc ^ (r&7); row 512B
    auto cpa64x128 = [&](uint32_t dstb, const float* src) {
        #pragma unroll
        for (int i = 0; i < 16; i++) {
            int idx = tid + i * 128;
            int r = idx >> 5, kc = idx & 31;
            CP_ASYNC16(sb + dstb + r * 512 + ((kc ^ (r & 7)) << 4),
                       src + (size_t)r * HH + kc * 4);
        }
    };
    // VT tile 128(h) x 64(kv): row h (256B), chunk kc(0..15) -> kc ^ (h&7)
    auto cpa_vt = [&](int kt) {
        const float* src = vtg + kt * 64;
        #pragma unroll
        for (int i = 0; i < 16; i++) {
            int idx = tid + i * 128;
            int h = idx >> 4, kc = idx & 15;
            CP_ASYNC16(sb + AVT * 4 + h * 256 + ((kc ^ (h & 7)) << 4),
                       src + (size_t)h * TT + kc * 4);
        }
    };

    // Prologue
    cpa64x128(AQ * 4, qg + (size_t)q0 * HH);
    cpa64x128(AK * 4, kg);
    CP_COMMIT();                       // group: Q + K[0]
    cpa_vt(0);
    CP_COMMIT();                       // group: VT[0]

    // ldmatrix lane constants
    const uint32_t rl = lid & 7;
    const uint32_t kq = lid >> 3;                       // 0..3
    const uint32_t hi4 = lid >> 4;                      // 0..1
    const uint32_t qrl16 = lid & 15;
    const uint32_t qxor = qrl16 & 7;
    const uint32_t qbase = sb + AQ * 4 + (r0w + qrl16) * 512;
    const uint32_t kbase = sb + AK * 4 + rl * 512;
    const uint32_t prow = (uint32_t)r0w + (((lid >> 3) & 1) << 3) + rl;
    const uint32_t p_base = sb + AP * 4 + prow * 256;
    const uint32_t vhalf = hi4 << 3;                    // 0 or 8
    const uint32_t vch = ((lid >> 3) & 1);              // kv chunk parity

    float o[16][4];
    #pragma unroll
    for (int nt = 0; nt < 16; nt++)
        #pragma unroll
        for (int j = 0; j < 4; j++) o[nt][j] = 0.0f;
    float m0s = -1e30f, m1s = -1e30f, l0 = 0.0f, l1 = 0.0f;

    const float sc = 0.08838834764831845f;
    const int grow0 = q0 + r0w + g;
    const int grow1 = grow0 + 8;

    for (int kt = 0; kt <= qt; ++kt) {
        CP_WAIT1();                    // K[kt] (and Q) ready; VT may fly
        __syncthreads();

        // ---- S = Q K^T ----
        float sa[8][4];
        #pragma unroll
        for (int nt = 0; nt < 8; nt++)
            #pragma unroll
            for (int j = 0; j < 4; j++) sa[nt][j] = 0.0f;

        #pragma unroll
        for (int kp = 0; kp < 8; kp++) {
            uint32_t qf0[4], qf1[4];
            ldsm_x4(qf0, qbase + (((4 * kp + hi4) ^ qxor) << 4));
            ldsm_x4(qf1, qbase + (((4 * kp + 2 + hi4) ^ qxor) << 4));
            const uint32_t kcsw = (((kp * 4 + kq) ^ rl) << 4);
            #pragma unroll
            for (int nt = 0; nt < 8; nt++) {
                uint32_t b4[4];
                ldsm_x4(b4, kbase + nt * 4096 + kcsw);
                mma_tf32(sa[nt], qf0, b4[0], b4[1]);
                mma_tf32(sa[nt], qf1, b4[2], b4[3]);
            }
        }

        __syncthreads();               // all warps done reading K[kt]
        if (kt < qt) {                 // overlap K[kt+1] load with softmax + PV
            cpa64x128(AK * 4, kg + (size_t)(kt + 1) * 64 * HH);
            CP_COMMIT();
        }

        // scale + causal mask
        const int k0 = kt * 64;
        #pragma unroll
        for (int nt = 0; nt < 8; nt++)
            #pragma unroll
            for (int j = 0; j < 4; j++) sa[nt][j] *= sc;
        if (kt == qt) {
            #pragma unroll
            for (int nt = 0; nt < 8; nt++) {
                int colb = k0 + nt * 8 + 2 * c;
                if (colb     > grow0) sa[nt][0] = -1e30f;
                if (colb + 1 > grow0) sa[nt][1] = -1e30f;
                if (colb     > grow1) sa[nt][2] = -1e30f;
                if (colb + 1 > grow1) sa[nt][3] = -1e30f;
            }
        }

        // online softmax
        float mt0 = -1e30f, mt1 = -1e30f;
        #pragma unroll
        for (int nt = 0; nt < 8; nt++) {
            mt0 = fmaxf(mt0, fmaxf(sa[nt][0], sa[nt][1]));
            mt1 = fmaxf(mt1, fmaxf(sa[nt][2], sa[nt][3]));
        }
        mt0 = fmaxf(mt0, __shfl_xor_sync(0xffffffffu, mt0, 1));
        mt0 = fmaxf(mt0, __shfl_xor_sync(0xffffffffu, mt0, 2));
        mt1 = fmaxf(mt1, __shfl_xor_sync(0xffffffffu, mt1, 1));
        mt1 = fmaxf(mt1, __shfl_xor_sync(0xffffffffu, mt1, 2));

        const float mn0 = fmaxf(m0s, mt0);
        const float mn1 = fmaxf(m1s, mt1);
        const float al0 = __expf(m0s - mn0);
        const float al1 = __expf(m1s - mn1);
        m0s = mn0; m1s = mn1;

        float lt0 = 0.0f, lt1 = 0.0f;
        #pragma unroll
        for (int nt = 0; nt < 8; nt++) {
            sa[nt][0] = __expf(sa[nt][0] - mn0);
            sa[nt][1] = __expf(sa[nt][1] - mn0);
            sa[nt][2] = __expf(sa[nt][2] - mn1);
            sa[nt][3] = __expf(sa[nt][3] - mn1);
            lt0 += sa[nt][0] + sa[nt][1];
            lt1 += sa[nt][2] + sa[nt][3];
        }
        lt0 += __shfl_xor_sync(0xffffffffu, lt0, 1);
        lt0 += __shfl_xor_sync(0xffffffffu, lt0, 2);
        lt1 += __shfl_xor_sync(0xffffffffu, lt1, 1);
        lt1 += __shfl_xor_sync(0xffffffffu, lt1, 2);
        l0 = l0 * al0 + lt0;
        l1 = l1 * al1 + lt1;

        #pragma unroll
        for (int nt = 0; nt < 16; nt++) {
            o[nt][0] *= al0; o[nt][1] *= al0;
            o[nt][2] *= al1; o[nt][3] *= al1;
        }

        // VT[kt] ready?
        if (kt < qt) CP_WAIT1(); else CP_WAIT0();
        __syncthreads();

        // P -> smem (tf32-rounded), warp-private rows, stride 64 + XOR swizzle
        {
            const int pr0 = AP + (r0w + g) * 64;
            const int pr8 = AP + (r0w + g + 8) * 64;
            const int foff = 2 * (c & 1);
            #pragma unroll
            for (int nt = 0; nt < 8; nt++) {
                const int grp = ((2 * nt + (c >> 1)) ^ g) << 2;
                float2 v0 = make_float2(f2tff(sa[nt][0]), f2tff(sa[nt][1]));
                float2 v1 = make_float2(f2tff(sa[nt][2]), f2tff(sa[nt][3]));
                *reinterpret_cast<float2*>(&sm[pr0 + grp + foff]) = v0;
                *reinterpret_cast<float2*>(&sm[pr8 + grp + foff]) = v1;
            }
        }
        __syncwarp();

        // ---- O += P V  (V B-frags via ldmatrix from VT) ----
        #pragma unroll
        for (int ks2 = 0; ks2 < 8; ks2++) {
            uint32_t pa[4];
            ldsm_x4(pa, p_base + ((((uint32_t)(2 * ks2) + hi4) ^ rl) << 4));
            const uint32_t ch = 2 * ks2 + vch;
            #pragma unroll
            for (int ntp = 0; ntp < 8; ntp++) {
                uint32_t vb[4];
                const uint32_t vrow = ntp * 16 + vhalf + rl;
                ldsm_x4(vb, sb + AVT * 4 + vrow * 256 + ((ch ^ rl) << 4));
                mma_tf32(o[2 * ntp],     pa, vb[0], vb[1]);
                mma_tf32(o[2 * ntp + 1], pa, vb[2], vb[3]);
            }
        }
        __syncthreads();               // all warps done with VT[kt] and P

        if (kt < qt) {
            cpa_vt(kt + 1);
            CP_COMMIT();
        }
    }

    // Epilogue
    const float inv0 = 1.0f / l0;
    const float inv1 = 1.0f / l1;
    #pragma unroll
    for (int nt = 0; nt < 16; nt++) {
        int col = nt * 8 + 2 * c;
        float2 v0 = make_float2(o[nt][0] * inv0, o[nt][1] * inv0);
        float2 v1 = make_float2(o[nt][2] * inv1, o[nt][3] * inv1);
        *reinterpret_cast<float2*>(&out[((size_t)b * TT + grow0) * HH + col]) = v0;
        *reinterpret_cast<float2*>(&out[((size_t)b * TT + grow1) * HH + col]) = v1;
    }
}

// ---------------------------------------------------------------------------
extern "C" void kernel_launch(void* const* d_in, const int* in_sizes, int n_in,
                              void* d_out, int out_size)
{
    const float* x  = (const float*)d_in[0];
    const float* Wq = (const float*)d_in[1];
    const float* Wk = (const float*)d_in[2];
    const float* Wv = (const float*)d_in[3];
    float* out = (float*)d_out;

    cudaFuncSetAttribute(qkv_mma_kernel, cudaFuncAttributeMaxDynamicSharedMemorySize,
                         QKV_SMEM_BYTES);
    cudaFuncSetAttribute(attn_mma_kernel, cudaFuncAttributeMaxDynamicSharedMemorySize,
                         ATT_SMEM_BYTES);

    dim3 g1((BB * TT) / 128, 3);
    qkv_mma_kernel<<<g1, 256, QKV_SMEM_BYTES>>>(x, Wq, Wk, Wv);

    dim3 g2(TT / 64, BB);
    attn_mma_kernel<<<g2, 128, ATT_SMEM_BYTES>>>(out);
}

// round 8
// speedup vs baseline: 1.4475x; 1.4475x over previous
#include <cuda_runtime.h>
#include <cuda_fp16.h>
#include <math.h>
#include <stdint.h>

#define BB 8
#define TT 2048
#define CC 1024
#define HH 128

__device__ __align__(16) __half g_q[BB * TT * HH];
__device__ __align__(16) __half g_k[BB * TT * HH];
__device__ __align__(16) __half g_vt[BB * HH * TT];   // V transposed: [b][h][t]

// ---------------------------------------------------------------------------
// PTX helpers
// ---------------------------------------------------------------------------
__device__ __forceinline__ void mma_f16(float c[4], const uint32_t a[4],
                                        uint32_t b0, uint32_t b1) {
    asm volatile(
        "mma.sync.aligned.m16n8k16.row.col.f32.f16.f16.f32 "
        "{%0,%1,%2,%3}, {%4,%5,%6,%7}, {%8,%9}, {%0,%1,%2,%3};"
        : "+f"(c[0]), "+f"(c[1]), "+f"(c[2]), "+f"(c[3])
        : "r"(a[0]), "r"(a[1]), "r"(a[2]), "r"(a[3]), "r"(b0), "r"(b1));
}

__device__ __forceinline__ void ldsm_x4(uint32_t r[4], uint32_t addr) {
    asm volatile("ldmatrix.sync.aligned.m8n8.x4.shared.b16 {%0,%1,%2,%3}, [%4];"
        : "=r"(r[0]), "=r"(r[1]), "=r"(r[2]), "=r"(r[3]) : "r"(addr));
}

__device__ __forceinline__ uint32_t smem_u32(const void* p) {
    uint32_t a;
    asm("{ .reg .u64 t; cvta.to.shared.u64 t, %1; cvt.u32.u64 %0, t; }" : "=r"(a) : "l"(p));
    return a;
}

#define CP_ASYNC16(dst, src) \
    asm volatile("cp.async.cg.shared.global [%0], [%1], 16;" :: "r"(dst), "l"(src) : "memory")
#define CP_COMMIT() asm volatile("cp.async.commit_group;" ::: "memory")
#define CP_WAIT0()  asm volatile("cp.async.wait_group 0;" ::: "memory")
#define CP_WAIT1()  asm volatile("cp.async.wait_group 1;" ::: "memory")
#define CP_WAIT2()  asm volatile("cp.async.wait_group 2;" ::: "memory")

__device__ __forceinline__ uint32_t h2u(float a, float b) {
    __half2 h = __floats2half2_rn(a, b);
    return *reinterpret_cast<uint32_t*>(&h);
}

// ===========================================================================
// Kernel 1: QKV projection, fp16 mma m16n8k16 (unchanged from R7).
// out[r][h] = sum_c x[r][c] * W[h][c].  M=16384, N=128, K=1024.
// BM=128, BN=128, BK=32. 256 threads = 8 warps (4 M x 2 N), warp 32x64.
// Smem: A/B tiles 128 rows x 32 halfs, padded to 80B rows, double buffered.
// ===========================================================================
#define QKV_BUF 10240            // bytes per (matrix, stage): 128 rows * 80B
#define QKV_SMEM_BYTES (4 * QKV_BUF)

__global__ __launch_bounds__(256, 2) void qkv_mma_kernel(
    const float* __restrict__ x,
    const float* __restrict__ Wq,
    const float* __restrict__ Wk,
    const float* __restrict__ Wv)
{
    extern __shared__ char smc[];
    const uint32_t sb = smem_u32(smc);
    const int mat = blockIdx.y;
    const float* W = (mat == 0) ? Wq : (mat == 1) ? Wk : Wv;

    const int tid = threadIdx.x;
    const int lid = tid & 31;
    const int wid = tid >> 5;
    const int g = lid >> 2;
    const int c = lid & 3;
    const int wm = wid & 3;
    const int wn = wid >> 2;
    const int m0 = blockIdx.x * 128;

    const uint32_t lrow = lid & 15;
    const uint32_t lhi  = lid >> 4;

    float acc[2][8][4];
    #pragma unroll
    for (int mi = 0; mi < 2; mi++)
        #pragma unroll
        for (int ni = 0; ni < 8; ni++)
            #pragma unroll
            for (int j = 0; j < 4; j++) acc[mi][ni][j] = 0.0f;

    float4 xr[4], wr[4];

    auto loadT = [&](int it) {
        const int k0 = it * 32;
        #pragma unroll
        for (int i = 0; i < 2; i++) {
            int idx = tid + i * 256;
            int row = idx >> 2;
            int ch  = idx & 3;
            const float* px = &x[(size_t)(m0 + row) * CC + k0 + ch * 8];
            const float* pw = &W[(size_t)row * CC + k0 + ch * 8];
            xr[2 * i]     = *reinterpret_cast<const float4*>(px);
            xr[2 * i + 1] = *reinterpret_cast<const float4*>(px + 4);
            wr[2 * i]     = *reinterpret_cast<const float4*>(pw);
            wr[2 * i + 1] = *reinterpret_cast<const float4*>(pw + 4);
        }
    };
    auto stsT = [&](int p) {
        #pragma unroll
        for (int i = 0; i < 2; i++) {
            int idx = tid + i * 256;
            int row = idx >> 2;
            int ch  = idx & 3;
            uint4 ua = make_uint4(h2u(xr[2*i].x, xr[2*i].y), h2u(xr[2*i].z, xr[2*i].w),
                                  h2u(xr[2*i+1].x, xr[2*i+1].y), h2u(xr[2*i+1].z, xr[2*i+1].w));
            uint4 ub = make_uint4(h2u(wr[2*i].x, wr[2*i].y), h2u(wr[2*i].z, wr[2*i].w),
                                  h2u(wr[2*i+1].x, wr[2*i+1].y), h2u(wr[2*i+1].z, wr[2*i+1].w));
            *reinterpret_cast<uint4*>(smc + p * QKV_BUF + row * 80 + ch * 16) = ua;
            *reinterpret_cast<uint4*>(smc + 2 * QKV_BUF + p * QKV_BUF + row * 80 + ch * 16) = ub;
        }
    };

    loadT(0);
    stsT(0);
    __syncthreads();

    for (int it = 0; it < 32; ++it) {
        const int p = it & 1;
        if (it < 31) loadT(it + 1);

        const uint32_t abase = sb + p * QKV_BUF;
        const uint32_t bbase = sb + 2 * QKV_BUF + p * QKV_BUF;

        #pragma unroll
        for (int ks = 0; ks < 2; ks++) {
            const uint32_t choff = (ks * 2 + lhi) * 16;
            uint32_t a0[4], a1[4];
            ldsm_x4(a0, abase + (wm * 32 + lrow) * 80 + choff);
            ldsm_x4(a1, abase + (wm * 32 + 16 + lrow) * 80 + choff);
            #pragma unroll
            for (int nt2 = 0; nt2 < 4; nt2++) {
                uint32_t b4[4];
                ldsm_x4(b4, bbase + (wn * 64 + nt2 * 16 + lrow) * 80 + choff);
                mma_f16(acc[0][2 * nt2],     a0, b4[0], b4[2]);
                mma_f16(acc[0][2 * nt2 + 1], a0, b4[1], b4[3]);
                mma_f16(acc[1][2 * nt2],     a1, b4[0], b4[2]);
                mma_f16(acc[1][2 * nt2 + 1], a1, b4[1], b4[3]);
            }
        }

        if (it < 31) stsT(p ^ 1);
        __syncthreads();
    }

    if (mat < 2) {
        __half* out = (mat == 0) ? g_q : g_k;
        #pragma unroll
        for (int mi = 0; mi < 2; mi++) {
            int row0 = m0 + wm * 32 + mi * 16 + g;
            int row1 = row0 + 8;
            #pragma unroll
            for (int ni = 0; ni < 8; ni++) {
                int col = wn * 64 + ni * 8 + 2 * c;
                *reinterpret_cast<uint32_t*>(&out[(size_t)row0 * HH + col]) =
                    h2u(acc[mi][ni][0], acc[mi][ni][1]);
                *reinterpret_cast<uint32_t*>(&out[(size_t)row1 * HH + col]) =
                    h2u(acc[mi][ni][2], acc[mi][ni][3]);
            }
        }
    } else {
        __half* vtb = g_vt + (size_t)(m0 / TT) * HH * TT;
        const int tbase = m0 % TT;
        #pragma unroll
        for (int mi = 0; mi < 2; mi++) {
            int t0 = tbase + wm * 32 + mi * 16 + g;
            int t1 = t0 + 8;
            #pragma unroll
            for (int ni = 0; ni < 8; ni++) {
                int col = wn * 64 + ni * 8 + 2 * c;
                vtb[(size_t)col * TT + t0]       = __float2half_rn(acc[mi][ni][0]);
                vtb[(size_t)(col + 1) * TT + t0] = __float2half_rn(acc[mi][ni][1]);
                vtb[(size_t)col * TT + t1]       = __float2half_rn(acc[mi][ni][2]);
                vtb[(size_t)(col + 1) * TT + t1] = __float2half_rn(acc[mi][ni][3]);
            }
        }
    }
}

// ===========================================================================
// Kernel 2: causal flash attention, fp16 m16n8k16, PADDED strides (no XOR).
// BQ=BKV=64, 128 threads (4 warps), warp = 16 q-rows x full 64 kv / 128 h.
// Row strides: Q/K 272B (64 rows), VT/P 144B. All 16B-aligned; stride mod
// 128B = 16 -> ldmatrix 8-row column spans 32 distinct banks.
// Smem: Q 17408 + K x2 17408 + VT x2 18432 + P 9216 = 98304 B -> 2 CTAs/SM.
// ===========================================================================
#define QSTR  272
#define VSTR  144
#define AQb   0
#define AK0b  17408
#define AK1b  34816
#define AVT0b 52224
#define AVT1b 70656
#define APb   89088
#define ATT_SMEM_BYTES 98304

__global__ __launch_bounds__(128, 2) void attn_mma_kernel(float* __restrict__ out)
{
    extern __shared__ char smc[];
    const uint32_t sb = smem_u32(smc);

    const int b  = blockIdx.y;
    const int qt = (gridDim.x - 1) - blockIdx.x;   // heavy tiles first
    const int q0 = qt * 64;
    const int tid = threadIdx.x;
    const int wid = tid >> 5;
    const int lid = tid & 31;
    const int g = lid >> 2;
    const int c = lid & 3;
    const int r0w = wid * 16;

    const __half* qg  = g_q  + (size_t)b * TT * HH;
    const __half* kg  = g_k  + (size_t)b * TT * HH;
    const __half* vtg = g_vt + (size_t)b * HH * TT;

    // 64(rows) x 128(halfs) tile, 16 chunks/row, padded stride 272B
    auto cpa64 = [&](uint32_t dstb, const __half* src) {
        #pragma unroll
        for (int i = 0; i < 8; i++) {
            int idx = tid + i * 128;
            int r = idx >> 4, ch = idx & 15;
            CP_ASYNC16(sb + dstb + r * QSTR + ch * 16,
                       src + (size_t)r * HH + ch * 8);
        }
    };
    // VT tile 128(h) x 64(kv), 8 chunks/row, padded stride 144B
    auto cpa_vt = [&](uint32_t dstb, int kt) {
        const __half* src = vtg + kt * 64;
        #pragma unroll
        for (int i = 0; i < 8; i++) {
            int idx = tid + i * 128;
            int r = idx >> 3, ch = idx & 7;
            CP_ASYNC16(sb + dstb + r * VSTR + ch * 16,
                       src + (size_t)r * TT + ch * 8);
        }
    };

    // Prologue
    cpa64(AQb, qg + (size_t)q0 * HH);
    cpa64(AK0b, kg);
    CP_COMMIT();                       // group: Q + K0
    cpa_vt(AVT0b, 0);
    CP_COMMIT();                       // group: VT0
    CP_WAIT1();
    __syncthreads();

    const uint32_t lrow = lid & 15;
    const uint32_t lhi  = lid >> 4;

    // Q fragments (8 k-steps of 16), loaded once
    uint32_t qa[8][4];
    {
        const uint32_t qrb = sb + AQb + (r0w + lrow) * QSTR;
        #pragma unroll
        for (int ks = 0; ks < 8; ks++)
            ldsm_x4(qa[ks], qrb + (ks * 2 + lhi) * 16);
    }

    float o[16][4];
    #pragma unroll
    for (int nt = 0; nt < 16; nt++)
        #pragma unroll
        for (int j = 0; j < 4; j++) o[nt][j] = 0.0f;
    float m0s = -1e30f, m1s = -1e30f, l0 = 0.0f, l1 = 0.0f;

    const float sc = 0.08838834764831845f;
    const int grow0 = q0 + r0w + g;
    const int grow1 = grow0 + 8;

    for (int kt = 0; kt <= qt; ++kt) {
        const int p = kt & 1;
        const uint32_t kbase  = sb + (p ? AK1b : AK0b);
        const uint32_t vtbase = sb + (p ? AVT1b : AVT0b);

        if (kt < qt) {
            cpa64(p ? AK0b : AK1b, kg + (size_t)(kt + 1) * 64 * HH);
            CP_COMMIT();
            cpa_vt(p ? AVT0b : AVT1b, kt + 1);
            CP_COMMIT();
            CP_WAIT2();                // K[kt], VT[kt] arrived
        } else {
            CP_WAIT0();
        }
        __syncthreads();

        // ---- S = Q K^T ----
        float sa[8][4];
        #pragma unroll
        for (int nt = 0; nt < 8; nt++)
            #pragma unroll
            for (int j = 0; j < 4; j++) sa[nt][j] = 0.0f;

        #pragma unroll
        for (int ks = 0; ks < 8; ks++) {
            const uint32_t choff = (ks * 2 + lhi) * 16;
            #pragma unroll
            for (int nt2 = 0; nt2 < 4; nt2++) {
                uint32_t kb[4];
                ldsm_x4(kb, kbase + (nt2 * 16 + lrow) * QSTR + choff);
                mma_f16(sa[2 * nt2],     qa[ks], kb[0], kb[2]);
                mma_f16(sa[2 * nt2 + 1], qa[ks], kb[1], kb[3]);
            }
        }

        // scale + causal mask
        const int k0 = kt * 64;
        #pragma unroll
        for (int nt = 0; nt < 8; nt++)
            #pragma unroll
            for (int j = 0; j < 4; j++) sa[nt][j] *= sc;
        if (kt == qt) {
            #pragma unroll
            for (int nt = 0; nt < 8; nt++) {
                int colb = k0 + nt * 8 + 2 * c;
                if (colb     > grow0) sa[nt][0] = -1e30f;
                if (colb + 1 > grow0) sa[nt][1] = -1e30f;
                if (colb     > grow1) sa[nt][2] = -1e30f;
                if (colb + 1 > grow1) sa[nt][3] = -1e30f;
            }
        }

        // online softmax
        float mt0 = -1e30f, mt1 = -1e30f;
        #pragma unroll
        for (int nt = 0; nt < 8; nt++) {
            mt0 = fmaxf(mt0, fmaxf(sa[nt][0], sa[nt][1]));
            mt1 = fmaxf(mt1, fmaxf(sa[nt][2], sa[nt][3]));
        }
        mt0 = fmaxf(mt0, __shfl_xor_sync(0xffffffffu, mt0, 1));
        mt0 = fmaxf(mt0, __shfl_xor_sync(0xffffffffu, mt0, 2));
        mt1 = fmaxf(mt1, __shfl_xor_sync(0xffffffffu, mt1, 1));
        mt1 = fmaxf(mt1, __shfl_xor_sync(0xffffffffu, mt1, 2));

        const float mn0 = fmaxf(m0s, mt0);
        const float mn1 = fmaxf(m1s, mt1);
        const float al0 = __expf(m0s - mn0);
        const float al1 = __expf(m1s - mn1);
        m0s = mn0; m1s = mn1;

        float lt0 = 0.0f, lt1 = 0.0f;
        #pragma unroll
        for (int nt = 0; nt < 8; nt++) {
            sa[nt][0] = __expf(sa[nt][0] - mn0);
            sa[nt][1] = __expf(sa[nt][1] - mn0);
            sa[nt][2] = __expf(sa[nt][2] - mn1);
            sa[nt][3] = __expf(sa[nt][3] - mn1);
            lt0 += sa[nt][0] + sa[nt][1];
            lt1 += sa[nt][2] + sa[nt][3];
        }
        lt0 += __shfl_xor_sync(0xffffffffu, lt0, 1);
        lt0 += __shfl_xor_sync(0xffffffffu, lt0, 2);
        lt1 += __shfl_xor_sync(0xffffffffu, lt1, 1);
        lt1 += __shfl_xor_sync(0xffffffffu, lt1, 2);
        l0 = l0 * al0 + lt0;
        l1 = l1 * al1 + lt1;

        #pragma unroll
        for (int nt = 0; nt < 16; nt++) {
            o[nt][0] *= al0; o[nt][1] *= al0;
            o[nt][2] *= al1; o[nt][3] *= al1;
        }

        // P -> smem fp16 (warp-private rows, padded 144B rows, no swizzle)
        {
            char* pr0 = smc + APb + (r0w + g) * VSTR + c * 4;
            char* pr8 = pr0 + 8 * VSTR;
            #pragma unroll
            for (int nt = 0; nt < 8; nt++) {
                *reinterpret_cast<uint32_t*>(pr0 + nt * 16) = h2u(sa[nt][0], sa[nt][1]);
                *reinterpret_cast<uint32_t*>(pr8 + nt * 16) = h2u(sa[nt][2], sa[nt][3]);
            }
        }
        __syncwarp();

        // ---- O += P V ----
        #pragma unroll
        for (int ks2 = 0; ks2 < 4; ks2++) {
            const uint32_t choff = (ks2 * 2 + lhi) * 16;
            uint32_t pa[4];
            ldsm_x4(pa, sb + APb + (r0w + lrow) * VSTR + choff);
            #pragma unroll
            for (int ntv = 0; ntv < 8; ntv++) {
                uint32_t vb[4];
                ldsm_x4(vb, vtbase + (ntv * 16 + lrow) * VSTR + choff);
                mma_f16(o[2 * ntv],     pa, vb[0], vb[2]);
                mma_f16(o[2 * ntv + 1], pa, vb[1], vb[3]);
            }
        }
        __syncthreads();               // buffers free for next prefetch
    }

    // Epilogue
    const float inv0 = 1.0f / l0;
    const float inv1 = 1.0f / l1;
    #pragma unroll
    for (int nt = 0; nt < 16; nt++) {
        int col = nt * 8 + 2 * c;
        float2 v0 = make_float2(o[nt][0] * inv0, o[nt][1] * inv0);
        float2 v1 = make_float2(o[nt][2] * inv1, o[nt][3] * inv1);
        *reinterpret_cast<float2*>(&out[((size_t)b * TT + grow0) * HH + col]) = v0;
        *reinterpret_cast<float2*>(&out[((size_t)b * TT + grow1) * HH + col]) = v1;
    }
}

// ---------------------------------------------------------------------------
extern "C" void kernel_launch(void* const* d_in, const int* in_sizes, int n_in,
                              void* d_out, int out_size)
{
    const float* x  = (const float*)d_in[0];
    const float* Wq = (const float*)d_in[1];
    const float* Wk = (const float*)d_in[2];
    const float* Wv = (const float*)d_in[3];
    float* out = (float*)d_out;

    cudaFuncSetAttribute(qkv_mma_kernel, cudaFuncAttributeMaxDynamicSharedMemorySize,
                         QKV_SMEM_BYTES);
    cudaFuncSetAttribute(attn_mma_kernel, cudaFuncAttributeMaxDynamicSharedMemorySize,
                         ATT_SMEM_BYTES);

    dim3 g1((BB * TT) / 128, 3);
    qkv_mma_kernel<<<g1, 256, QKV_SMEM_BYTES>>>(x, Wq, Wk, Wv);

    dim3 g2(TT / 64, BB);
    attn_mma_kernel<<<g2, 128, ATT_SMEM_BYTES>>>(out);
}

// round 9
// speedup vs baseline: 1.5934x; 1.1008x over previous
#include <cuda_runtime.h>
#include <cuda_fp16.h>
#include <math.h>
#include <stdint.h>

#define BB 8
#define TT 2048
#define CC 1024
#define HH 128

__device__ __align__(16) __half g_q[BB * TT * HH];
__device__ __align__(16) __half g_k[BB * TT * HH];
__device__ __align__(16) __half g_vt[BB * HH * TT];   // V transposed: [b][h][t]
__device__ __align__(16) __half g_xh[BB * TT * CC];   // x in fp16
__device__ __align__(16) __half g_wh[3 * HH * CC];    // Wq/Wk/Wv in fp16

// ---------------------------------------------------------------------------
// PTX helpers
// ---------------------------------------------------------------------------
__device__ __forceinline__ void mma_f16(float c[4], const uint32_t a[4],
                                        uint32_t b0, uint32_t b1) {
    asm volatile(
        "mma.sync.aligned.m16n8k16.row.col.f32.f16.f16.f32 "
        "{%0,%1,%2,%3}, {%4,%5,%6,%7}, {%8,%9}, {%0,%1,%2,%3};"
        : "+f"(c[0]), "+f"(c[1]), "+f"(c[2]), "+f"(c[3])
        : "r"(a[0]), "r"(a[1]), "r"(a[2]), "r"(a[3]), "r"(b0), "r"(b1));
}

__device__ __forceinline__ void ldsm_x4(uint32_t r[4], uint32_t addr) {
    asm volatile("ldmatrix.sync.aligned.m8n8.x4.shared.b16 {%0,%1,%2,%3}, [%4];"
        : "=r"(r[0]), "=r"(r[1]), "=r"(r[2]), "=r"(r[3]) : "r"(addr));
}

__device__ __forceinline__ uint32_t smem_u32(const void* p) {
    uint32_t a;
    asm("{ .reg .u64 t; cvta.to.shared.u64 t, %1; cvt.u32.u64 %0, t; }" : "=r"(a) : "l"(p));
    return a;
}

#define CP_ASYNC16(dst, src) \
    asm volatile("cp.async.cg.shared.global [%0], [%1], 16;" :: "r"(dst), "l"(src) : "memory")
#define CP_COMMIT() asm volatile("cp.async.commit_group;" ::: "memory")
#define CP_WAIT0()  asm volatile("cp.async.wait_group 0;" ::: "memory")
#define CP_WAIT1()  asm volatile("cp.async.wait_group 1;" ::: "memory")
#define CP_WAIT2()  asm volatile("cp.async.wait_group 2;" ::: "memory")

__device__ __forceinline__ uint32_t h2u(float a, float b) {
    __half2 h = __floats2half2_rn(a, b);
    return *reinterpret_cast<uint32_t*>(&h);
}

// ===========================================================================
// Kernel 0: fp32 -> fp16 conversion (x and the three W matrices).
// which: 0 -> g_xh, 1..3 -> g_wh slice.  n8 = element count / 8.
// ===========================================================================
__global__ __launch_bounds__(256) void conv_f2h(
    const float4* __restrict__ src, int which, int n8)
{
    int i = blockIdx.x * 256 + threadIdx.x;
    if (i >= n8) return;
    __half* dst = (which == 0) ? g_xh : g_wh + (size_t)(which - 1) * (HH * CC);
    float4 a = src[2 * i];
    float4 b = src[2 * i + 1];
    uint4 o = make_uint4(h2u(a.x, a.y), h2u(a.z, a.w),
                         h2u(b.x, b.y), h2u(b.z, b.w));
    reinterpret_cast<uint4*>(dst)[i] = o;
}

// ===========================================================================
// Kernel 1: QKV projection, pure fp16, cp.async 2-stage, BK=64.
// out[r][h] = sum_c xh[r][c] * wh[h][c].  M=16384, N=128, K=1024.
// BM=128, BN=128. 256 threads = 8 warps (4 M x 2 N), warp 32x64.
// Smem: per stage A(128x64h, 144B rows) + B(same) = 36864B; x2 = 73728B.
// mat 0 -> g_q, 1 -> g_k, 2 -> g_vt (transposed), fp16.
// ===========================================================================
#define QKROW 144
#define QKB_OFF 18432            // B tile offset within stage
#define QKSTG 36864
#define QKV_SMEM_BYTES (2 * QKSTG)

__global__ __launch_bounds__(256, 2) void qkv_mma_kernel()
{
    extern __shared__ char smc[];
    const uint32_t sb = smem_u32(smc);
    const int mat = blockIdx.y;
    const __half* whm = g_wh + (size_t)mat * (HH * CC);

    const int tid = threadIdx.x;
    const int lid = tid & 31;
    const int wid = tid >> 5;
    const int g = lid >> 2;
    const int c = lid & 3;
    const int wm = wid & 3;
    const int wn = wid >> 2;
    const int m0 = blockIdx.x * 128;

    const uint32_t lrow = lid & 15;
    const uint32_t lhi  = lid >> 4;

    float acc[2][8][4];
    #pragma unroll
    for (int mi = 0; mi < 2; mi++)
        #pragma unroll
        for (int ni = 0; ni < 8; ni++)
            #pragma unroll
            for (int j = 0; j < 4; j++) acc[mi][ni][j] = 0.0f;

    // stage loader: 128 rows x 8 chunks for A and B each; 8 cp.async/thread
    auto cpa_stage = [&](int p, int kt) {
        const int k0 = kt * 64;
        const uint32_t base = sb + p * QKSTG;
        #pragma unroll
        for (int i = 0; i < 4; i++) {
            int idx = tid + i * 256;
            int r = idx >> 3, ch = idx & 7;
            CP_ASYNC16(base + r * QKROW + ch * 16,
                       g_xh + (size_t)(m0 + r) * CC + k0 + ch * 8);
            CP_ASYNC16(base + QKB_OFF + r * QKROW + ch * 16,
                       whm + (size_t)r * CC + k0 + ch * 8);
        }
    };

    cpa_stage(0, 0);
    CP_COMMIT();
    cpa_stage(1, 1);
    CP_COMMIT();
    CP_WAIT1();
    __syncthreads();

    for (int kt = 0; kt < 16; ++kt) {
        const int p = kt & 1;
        const uint32_t abase = sb + p * QKSTG;
        const uint32_t bbase = abase + QKB_OFF;

        #pragma unroll
        for (int ks = 0; ks < 4; ks++) {
            const uint32_t choff = (ks * 2 + lhi) * 16;
            uint32_t a0[4], a1[4];
            ldsm_x4(a0, abase + (wm * 32 + lrow) * QKROW + choff);
            ldsm_x4(a1, abase + (wm * 32 + 16 + lrow) * QKROW + choff);
            #pragma unroll
            for (int nt2 = 0; nt2 < 4; nt2++) {
                uint32_t b4[4];
                ldsm_x4(b4, bbase + (wn * 64 + nt2 * 16 + lrow) * QKROW + choff);
                mma_f16(acc[0][2 * nt2],     a0, b4[0], b4[2]);
                mma_f16(acc[0][2 * nt2 + 1], a0, b4[1], b4[3]);
                mma_f16(acc[1][2 * nt2],     a1, b4[0], b4[2]);
                mma_f16(acc[1][2 * nt2 + 1], a1, b4[1], b4[3]);
            }
        }

        if (kt < 14) {
            __syncthreads();           // everyone done reading stage p
            cpa_stage(p, kt + 2);
            CP_COMMIT();
            CP_WAIT1();                // stage p^1 (for kt+1) arrived
            __syncthreads();
        } else if (kt == 14) {
            CP_WAIT0();
            __syncthreads();
        }
    }

    if (mat < 2) {
        __half* out = (mat == 0) ? g_q : g_k;
        #pragma unroll
        for (int mi = 0; mi < 2; mi++) {
            int row0 = m0 + wm * 32 + mi * 16 + g;
            int row1 = row0 + 8;
            #pragma unroll
            for (int ni = 0; ni < 8; ni++) {
                int col = wn * 64 + ni * 8 + 2 * c;
                *reinterpret_cast<uint32_t*>(&out[(size_t)row0 * HH + col]) =
                    h2u(acc[mi][ni][0], acc[mi][ni][1]);
                *reinterpret_cast<uint32_t*>(&out[(size_t)row1 * HH + col]) =
                    h2u(acc[mi][ni][2], acc[mi][ni][3]);
            }
        }
    } else {
        __half* vtb = g_vt + (size_t)(m0 / TT) * HH * TT;
        const int tbase = m0 % TT;
        #pragma unroll
        for (int mi = 0; mi < 2; mi++) {
            int t0 = tbase + wm * 32 + mi * 16 + g;
            int t1 = t0 + 8;
            #pragma unroll
            for (int ni = 0; ni < 8; ni++) {
                int col = wn * 64 + ni * 8 + 2 * c;
                vtb[(size_t)col * TT + t0]       = __float2half_rn(acc[mi][ni][0]);
                vtb[(size_t)(col + 1) * TT + t0] = __float2half_rn(acc[mi][ni][1]);
                vtb[(size_t)col * TT + t1]       = __float2half_rn(acc[mi][ni][2]);
                vtb[(size_t)(col + 1) * TT + t1] = __float2half_rn(acc[mi][ni][3]);
            }
        }
    }
}

// ===========================================================================
// Kernel 2: causal flash attention, fp16 m16n8k16, padded strides (R8 frame).
// Only change vs R8: exp -> exp2 with log2e folded into the scale.
// ===========================================================================
#define QSTR  272
#define VSTR  144
#define AQb   0
#define AK0b  17408
#define AK1b  34816
#define AVT0b 52224
#define AVT1b 70656
#define APb   89088
#define ATT_SMEM_BYTES 98304

__global__ __launch_bounds__(128, 2) void attn_mma_kernel(float* __restrict__ out)
{
    extern __shared__ char smc[];
    const uint32_t sb = smem_u32(smc);

    const int b  = blockIdx.y;
    const int qt = (gridDim.x - 1) - blockIdx.x;   // heavy tiles first
    const int q0 = qt * 64;
    const int tid = threadIdx.x;
    const int wid = tid >> 5;
    const int lid = tid & 31;
    const int g = lid >> 2;
    const int c = lid & 3;
    const int r0w = wid * 16;

    const __half* qg  = g_q  + (size_t)b * TT * HH;
    const __half* kg  = g_k  + (size_t)b * TT * HH;
    const __half* vtg = g_vt + (size_t)b * HH * TT;

    auto cpa64 = [&](uint32_t dstb, const __half* src) {
        #pragma unroll
        for (int i = 0; i < 8; i++) {
            int idx = tid + i * 128;
            int r = idx >> 4, ch = idx & 15;
            CP_ASYNC16(sb + dstb + r * QSTR + ch * 16,
                       src + (size_t)r * HH + ch * 8);
        }
    };
    auto cpa_vt = [&](uint32_t dstb, int kt) {
        const __half* src = vtg + kt * 64;
        #pragma unroll
        for (int i = 0; i < 8; i++) {
            int idx = tid + i * 128;
            int r = idx >> 3, ch = idx & 7;
            CP_ASYNC16(sb + dstb + r * VSTR + ch * 16,
                       src + (size_t)r * TT + ch * 8);
        }
    };

    // Prologue
    cpa64(AQb, qg + (size_t)q0 * HH);
    cpa64(AK0b, kg);
    CP_COMMIT();                       // group: Q + K0
    cpa_vt(AVT0b, 0);
    CP_COMMIT();                       // group: VT0
    CP_WAIT1();
    __syncthreads();

    const uint32_t lrow = lid & 15;
    const uint32_t lhi  = lid >> 4;

    uint32_t qa[8][4];
    {
        const uint32_t qrb = sb + AQb + (r0w + lrow) * QSTR;
        #pragma unroll
        for (int ks = 0; ks < 8; ks++)
            ldsm_x4(qa[ks], qrb + (ks * 2 + lhi) * 16);
    }

    float o[16][4];
    #pragma unroll
    for (int nt = 0; nt < 16; nt++)
        #pragma unroll
        for (int j = 0; j < 4; j++) o[nt][j] = 0.0f;
    float m0s = -1e30f, m1s = -1e30f, l0 = 0.0f, l1 = 0.0f;

    const float sc2 = 0.08838834764831845f * 1.4426950408889634f;  // /sqrt(128) * log2e
    const int grow0 = q0 + r0w + g;
    const int grow1 = grow0 + 8;

    for (int kt = 0; kt <= qt; ++kt) {
        const int p = kt & 1;
        const uint32_t kbase  = sb + (p ? AK1b : AK0b);
        const uint32_t vtbase = sb + (p ? AVT1b : AVT0b);

        if (kt < qt) {
            cpa64(p ? AK0b : AK1b, kg + (size_t)(kt + 1) * 64 * HH);
            CP_COMMIT();
            cpa_vt(p ? AVT0b : AVT1b, kt + 1);
            CP_COMMIT();
            CP_WAIT2();                // K[kt], VT[kt] arrived
        } else {
            CP_WAIT0();
        }
        __syncthreads();

        // ---- S = Q K^T ----
        float sa[8][4];
        #pragma unroll
        for (int nt = 0; nt < 8; nt++)
            #pragma unroll
            for (int j = 0; j < 4; j++) sa[nt][j] = 0.0f;

        #pragma unroll
        for (int ks = 0; ks < 8; ks++) {
            const uint32_t choff = (ks * 2 + lhi) * 16;
            #pragma unroll
            for (int nt2 = 0; nt2 < 4; nt2++) {
                uint32_t kb[4];
                ldsm_x4(kb, kbase + (nt2 * 16 + lrow) * QSTR + choff);
                mma_f16(sa[2 * nt2],     qa[ks], kb[0], kb[2]);
                mma_f16(sa[2 * nt2 + 1], qa[ks], kb[1], kb[3]);
            }
        }

        // scale (log2 units) + causal mask
        const int k0 = kt * 64;
        #pragma unroll
        for (int nt = 0; nt < 8; nt++)
            #pragma unroll
            for (int j = 0; j < 4; j++) sa[nt][j] *= sc2;
        if (kt == qt) {
            #pragma unroll
            for (int nt = 0; nt < 8; nt++) {
                int colb = k0 + nt * 8 + 2 * c;
                if (colb     > grow0) sa[nt][0] = -1e30f;
                if (colb + 1 > grow0) sa[nt][1] = -1e30f;
                if (colb     > grow1) sa[nt][2] = -1e30f;
                if (colb + 1 > grow1) sa[nt][3] = -1e30f;
            }
        }

        // online softmax (base-2)
        float mt0 = -1e30f, mt1 = -1e30f;
        #pragma unroll
        for (int nt = 0; nt < 8; nt++) {
            mt0 = fmaxf(mt0, fmaxf(sa[nt][0], sa[nt][1]));
            mt1 = fmaxf(mt1, fmaxf(sa[nt][2], sa[nt][3]));
        }
        mt0 = fmaxf(mt0, __shfl_xor_sync(0xffffffffu, mt0, 1));
        mt0 = fmaxf(mt0, __shfl_xor_sync(0xffffffffu, mt0, 2));
        mt1 = fmaxf(mt1, __shfl_xor_sync(0xffffffffu, mt1, 1));
        mt1 = fmaxf(mt1, __shfl_xor_sync(0xffffffffu, mt1, 2));

        const float mn0 = fmaxf(m0s, mt0);
        const float mn1 = fmaxf(m1s, mt1);
        const float al0 = exp2f(m0s - mn0);
        const float al1 = exp2f(m1s - mn1);
        m0s = mn0; m1s = mn1;

        float lt0 = 0.0f, lt1 = 0.0f;
        #pragma unroll
        for (int nt = 0; nt < 8; nt++) {
            sa[nt][0] = exp2f(sa[nt][0] - mn0);
            sa[nt][1] = exp2f(sa[nt][1] - mn0);
            sa[nt][2] = exp2f(sa[nt][2] - mn1);
            sa[nt][3] = exp2f(sa[nt][3] - mn1);
            lt0 += sa[nt][0] + sa[nt][1];
            lt1 += sa[nt][2] + sa[nt][3];
        }
        lt0 += __shfl_xor_sync(0xffffffffu, lt0, 1);
        lt0 += __shfl_xor_sync(0xffffffffu, lt0, 2);
        lt1 += __shfl_xor_sync(0xffffffffu, lt1, 1);
        lt1 += __shfl_xor_sync(0xffffffffu, lt1, 2);
        l0 = l0 * al0 + lt0;
        l1 = l1 * al1 + lt1;

        #pragma unroll
        for (int nt = 0; nt < 16; nt++) {
            o[nt][0] *= al0; o[nt][1] *= al0;
            o[nt][2] *= al1; o[nt][3] *= al1;
        }

        // P -> smem fp16 (warp-private rows, padded 144B rows)
        {
            char* pr0 = smc + APb + (r0w + g) * VSTR + c * 4;
            char* pr8 = pr0 + 8 * VSTR;
            #pragma unroll
            for (int nt = 0; nt < 8; nt++) {
                *reinterpret_cast<uint32_t*>(pr0 + nt * 16) = h2u(sa[nt][0], sa[nt][1]);
                *reinterpret_cast<uint32_t*>(pr8 + nt * 16) = h2u(sa[nt][2], sa[nt][3]);
            }
        }
        __syncwarp();

        // ---- O += P V ----
        #pragma unroll
        for (int ks2 = 0; ks2 < 4; ks2++) {
            const uint32_t choff = (ks2 * 2 + lhi) * 16;
            uint32_t pa[4];
            ldsm_x4(pa, sb + APb + (r0w + lrow) * VSTR + choff);
            #pragma unroll
            for (int ntv = 0; ntv < 8; ntv++) {
                uint32_t vb[4];
                ldsm_x4(vb, vtbase + (ntv * 16 + lrow) * VSTR + choff);
                mma_f16(o[2 * ntv],     pa, vb[0], vb[2]);
                mma_f16(o[2 * ntv + 1], pa, vb[1], vb[3]);
            }
        }
        __syncthreads();
    }

    // Epilogue
    const float inv0 = 1.0f / l0;
    const float inv1 = 1.0f / l1;
    #pragma unroll
    for (int nt = 0; nt < 16; nt++) {
        int col = nt * 8 + 2 * c;
        float2 v0 = make_float2(o[nt][0] * inv0, o[nt][1] * inv0);
        float2 v1 = make_float2(o[nt][2] * inv1, o[nt][3] * inv1);
        *reinterpret_cast<float2*>(&out[((size_t)b * TT + grow0) * HH + col]) = v0;
        *reinterpret_cast<float2*>(&out[((size_t)b * TT + grow1) * HH + col]) = v1;
    }
}

// ---------------------------------------------------------------------------
extern "C" void kernel_launch(void* const* d_in, const int* in_sizes, int n_in,
                              void* d_out, int out_size)
{
    const float* x  = (const float*)d_in[0];
    const float* Wq = (const float*)d_in[1];
    const float* Wk = (const float*)d_in[2];
    const float* Wv = (const float*)d_in[3];
    float* out = (float*)d_out;

    cudaFuncSetAttribute(qkv_mma_kernel, cudaFuncAttributeMaxDynamicSharedMemorySize,
                         QKV_SMEM_BYTES);
    cudaFuncSetAttribute(attn_mma_kernel, cudaFuncAttributeMaxDynamicSharedMemorySize,
                         ATT_SMEM_BYTES);

    // fp32 -> fp16 conversions
    conv_f2h<<<(BB * TT * CC / 8 + 255) / 256, 256>>>((const float4*)x, 0, BB * TT * CC / 8);
    conv_f2h<<<(HH * CC / 8 + 255) / 256, 256>>>((const float4*)Wq, 1, HH * CC / 8);
    conv_f2h<<<(HH * CC / 8 + 255) / 256, 256>>>((const float4*)Wk, 2, HH * CC / 8);
    conv_f2h<<<(HH * CC / 8 + 255) / 256, 256>>>((const float4*)Wv, 3, HH * CC / 8);

    dim3 g1((BB * TT) / 128, 3);
    qkv_mma_kernel<<<g1, 256, QKV_SMEM_BYTES>>>();

    dim3 g2(TT / 64, BB);
    attn_mma_kernel<<<g2, 128, ATT_SMEM_BYTES>>>(out);
}

// round 10
// speedup vs baseline: 1.8108x; 1.1364x over previous
#include <cuda_runtime.h>
#include <cuda_fp16.h>
#include <math.h>
#include <stdint.h>

#define BB 8
#define TT 2048
#define CC 1024
#define HH 128

__device__ __align__(16) __half g_q[BB * TT * HH];
__device__ __align__(16) __half g_k[BB * TT * HH];
__device__ __align__(16) __half g_vt[BB * HH * TT];   // V transposed: [b][h][t]
__device__ __align__(16) __half g_xh[BB * TT * CC];   // x in fp16
__device__ __align__(16) __half g_wh[3 * HH * CC];    // Wq/Wk/Wv in fp16

// Split-KV partials for heavy q-tiles (qt 16..31): O unnormalized + m,l
__device__ __align__(16) float g_po[BB][16][2][64][HH];   // 16 MB
__device__ __align__(16) float g_pm[BB][16][2][64];
__device__ __align__(16) float g_pl[BB][16][2][64];

// ---------------------------------------------------------------------------
// PTX helpers
// ---------------------------------------------------------------------------
__device__ __forceinline__ void mma_f16(float c[4], const uint32_t a[4],
                                        uint32_t b0, uint32_t b1) {
    asm volatile(
        "mma.sync.aligned.m16n8k16.row.col.f32.f16.f16.f32 "
        "{%0,%1,%2,%3}, {%4,%5,%6,%7}, {%8,%9}, {%0,%1,%2,%3};"
        : "+f"(c[0]), "+f"(c[1]), "+f"(c[2]), "+f"(c[3])
        : "r"(a[0]), "r"(a[1]), "r"(a[2]), "r"(a[3]), "r"(b0), "r"(b1));
}

__device__ __forceinline__ void ldsm_x4(uint32_t r[4], uint32_t addr) {
    asm volatile("ldmatrix.sync.aligned.m8n8.x4.shared.b16 {%0,%1,%2,%3}, [%4];"
        : "=r"(r[0]), "=r"(r[1]), "=r"(r[2]), "=r"(r[3]) : "r"(addr));
}

__device__ __forceinline__ uint32_t smem_u32(const void* p) {
    uint32_t a;
    asm("{ .reg .u64 t; cvta.to.shared.u64 t, %1; cvt.u32.u64 %0, t; }" : "=r"(a) : "l"(p));
    return a;
}

#define CP_ASYNC16(dst, src) \
    asm volatile("cp.async.cg.shared.global [%0], [%1], 16;" :: "r"(dst), "l"(src) : "memory")
#define CP_COMMIT() asm volatile("cp.async.commit_group;" ::: "memory")
#define CP_WAIT0()  asm volatile("cp.async.wait_group 0;" ::: "memory")
#define CP_WAIT1()  asm volatile("cp.async.wait_group 1;" ::: "memory")
#define CP_WAIT2()  asm volatile("cp.async.wait_group 2;" ::: "memory")

__device__ __forceinline__ uint32_t h2u(float a, float b) {
    __half2 h = __floats2half2_rn(a, b);
    return *reinterpret_cast<uint32_t*>(&h);
}

// ===========================================================================
// Kernel 0: fp32 -> fp16 conversion (x and the three W matrices).
// ===========================================================================
__global__ __launch_bounds__(256) void conv_f2h(
    const float4* __restrict__ src, int which, int n8)
{
    int i = blockIdx.x * 256 + threadIdx.x;
    if (i >= n8) return;
    __half* dst = (which == 0) ? g_xh : g_wh + (size_t)(which - 1) * (HH * CC);
    float4 a = src[2 * i];
    float4 b = src[2 * i + 1];
    uint4 o = make_uint4(h2u(a.x, a.y), h2u(a.z, a.w),
                         h2u(b.x, b.y), h2u(b.z, b.w));
    reinterpret_cast<uint4*>(dst)[i] = o;
}

// ===========================================================================
// Kernel 1: QKV projection, pure fp16, cp.async 2-stage, BK=64 (R9, unchanged).
// ===========================================================================
#define QKROW 144
#define QKB_OFF 18432
#define QKSTG 36864
#define QKV_SMEM_BYTES (2 * QKSTG)

__global__ __launch_bounds__(256, 2) void qkv_mma_kernel()
{
    extern __shared__ char smc[];
    const uint32_t sb = smem_u32(smc);
    const int mat = blockIdx.y;
    const __half* whm = g_wh + (size_t)mat * (HH * CC);

    const int tid = threadIdx.x;
    const int lid = tid & 31;
    const int wid = tid >> 5;
    const int g = lid >> 2;
    const int c = lid & 3;
    const int wm = wid & 3;
    const int wn = wid >> 2;
    const int m0 = blockIdx.x * 128;

    const uint32_t lrow = lid & 15;
    const uint32_t lhi  = lid >> 4;

    float acc[2][8][4];
    #pragma unroll
    for (int mi = 0; mi < 2; mi++)
        #pragma unroll
        for (int ni = 0; ni < 8; ni++)
            #pragma unroll
            for (int j = 0; j < 4; j++) acc[mi][ni][j] = 0.0f;

    auto cpa_stage = [&](int p, int kt) {
        const int k0 = kt * 64;
        const uint32_t base = sb + p * QKSTG;
        #pragma unroll
        for (int i = 0; i < 4; i++) {
            int idx = tid + i * 256;
            int r = idx >> 3, ch = idx & 7;
            CP_ASYNC16(base + r * QKROW + ch * 16,
                       g_xh + (size_t)(m0 + r) * CC + k0 + ch * 8);
            CP_ASYNC16(base + QKB_OFF + r * QKROW + ch * 16,
                       whm + (size_t)r * CC + k0 + ch * 8);
        }
    };

    cpa_stage(0, 0);
    CP_COMMIT();
    cpa_stage(1, 1);
    CP_COMMIT();
    CP_WAIT1();
    __syncthreads();

    for (int kt = 0; kt < 16; ++kt) {
        const int p = kt & 1;
        const uint32_t abase = sb + p * QKSTG;
        const uint32_t bbase = abase + QKB_OFF;

        #pragma unroll
        for (int ks = 0; ks < 4; ks++) {
            const uint32_t choff = (ks * 2 + lhi) * 16;
            uint32_t a0[4], a1[4];
            ldsm_x4(a0, abase + (wm * 32 + lrow) * QKROW + choff);
            ldsm_x4(a1, abase + (wm * 32 + 16 + lrow) * QKROW + choff);
            #pragma unroll
            for (int nt2 = 0; nt2 < 4; nt2++) {
                uint32_t b4[4];
                ldsm_x4(b4, bbase + (wn * 64 + nt2 * 16 + lrow) * QKROW + choff);
                mma_f16(acc[0][2 * nt2],     a0, b4[0], b4[2]);
                mma_f16(acc[0][2 * nt2 + 1], a0, b4[1], b4[3]);
                mma_f16(acc[1][2 * nt2],     a1, b4[0], b4[2]);
                mma_f16(acc[1][2 * nt2 + 1], a1, b4[1], b4[3]);
            }
        }

        if (kt < 14) {
            __syncthreads();
            cpa_stage(p, kt + 2);
            CP_COMMIT();
            CP_WAIT1();
            __syncthreads();
        } else if (kt == 14) {
            CP_WAIT0();
            __syncthreads();
        }
    }

    if (mat < 2) {
        __half* out = (mat == 0) ? g_q : g_k;
        #pragma unroll
        for (int mi = 0; mi < 2; mi++) {
            int row0 = m0 + wm * 32 + mi * 16 + g;
            int row1 = row0 + 8;
            #pragma unroll
            for (int ni = 0; ni < 8; ni++) {
                int col = wn * 64 + ni * 8 + 2 * c;
                *reinterpret_cast<uint32_t*>(&out[(size_t)row0 * HH + col]) =
                    h2u(acc[mi][ni][0], acc[mi][ni][1]);
                *reinterpret_cast<uint32_t*>(&out[(size_t)row1 * HH + col]) =
                    h2u(acc[mi][ni][2], acc[mi][ni][3]);
            }
        }
    } else {
        __half* vtb = g_vt + (size_t)(m0 / TT) * HH * TT;
        const int tbase = m0 % TT;
        #pragma unroll
        for (int mi = 0; mi < 2; mi++) {
            int t0 = tbase + wm * 32 + mi * 16 + g;
            int t1 = t0 + 8;
            #pragma unroll
            for (int ni = 0; ni < 8; ni++) {
                int col = wn * 64 + ni * 8 + 2 * c;
                vtb[(size_t)col * TT + t0]       = __float2half_rn(acc[mi][ni][0]);
                vtb[(size_t)(col + 1) * TT + t0] = __float2half_rn(acc[mi][ni][1]);
                vtb[(size_t)col * TT + t1]       = __float2half_rn(acc[mi][ni][2]);
                vtb[(size_t)(col + 1) * TT + t1] = __float2half_rn(acc[mi][ni][3]);
            }
        }
    }
}

// ===========================================================================
// Kernel 2: causal flash attention phase 1, split-KV.
// grid (48, 8).  widx 0..15 -> light qt=widx (direct write).
// widx 16..47 -> heavy qt=16+h/2, split=h&1, kv range halved; writes
// unnormalized O + per-row (m,l) partials.
// ===========================================================================
#define QSTR  272
#define VSTR  144
#define AQb   0
#define AK0b  17408
#define AK1b  34816
#define AVT0b 52224
#define AVT1b 70656
#define APb   89088
#define ATT_SMEM_BYTES 98304

__global__ __launch_bounds__(128, 2) void attn_mma_kernel(float* __restrict__ out)
{
    extern __shared__ char smc[];
    const uint32_t sb = smem_u32(smc);

    const int b  = blockIdx.y;
    const int widx = 47 - blockIdx.x;          // heavy splits scheduled first
    int qt, ktlo, kthi, split = 0, qh = 0;
    bool partial;
    if (widx < 16) {
        qt = widx; ktlo = 0; kthi = qt; partial = false;
    } else {
        int h = widx - 16;
        qh = h >> 1;
        qt = 16 + qh;
        split = h & 1;
        int first = (qt + 2) >> 1;             // tiles in split 0
        ktlo = split ? first : 0;
        kthi = split ? qt : first - 1;
        partial = true;
    }
    const int q0 = qt * 64;

    const int tid = threadIdx.x;
    const int wid = tid >> 5;
    const int lid = tid & 31;
    const int g = lid >> 2;
    const int c = lid & 3;
    const int r0w = wid * 16;

    const __half* qg  = g_q  + (size_t)b * TT * HH;
    const __half* kg  = g_k  + (size_t)b * TT * HH;
    const __half* vtg = g_vt + (size_t)b * HH * TT;

    auto cpa64 = [&](uint32_t dstb, const __half* src) {
        #pragma unroll
        for (int i = 0; i < 8; i++) {
            int idx = tid + i * 128;
            int r = idx >> 4, ch = idx & 15;
            CP_ASYNC16(sb + dstb + r * QSTR + ch * 16,
                       src + (size_t)r * HH + ch * 8);
        }
    };
    auto cpa_vt = [&](uint32_t dstb, int kt) {
        const __half* src = vtg + kt * 64;
        #pragma unroll
        for (int i = 0; i < 8; i++) {
            int idx = tid + i * 128;
            int r = idx >> 3, ch = idx & 7;
            CP_ASYNC16(sb + dstb + r * VSTR + ch * 16,
                       src + (size_t)r * TT + ch * 8);
        }
    };

    // Prologue
    cpa64(AQb, qg + (size_t)q0 * HH);
    cpa64(AK0b, kg + (size_t)ktlo * 64 * HH);
    CP_COMMIT();                       // group: Q + K[ktlo]
    cpa_vt(AVT0b, ktlo);
    CP_COMMIT();                       // group: VT[ktlo]
    CP_WAIT1();
    __syncthreads();

    const uint32_t lrow = lid & 15;
    const uint32_t lhi  = lid >> 4;

    uint32_t qa[8][4];
    {
        const uint32_t qrb = sb + AQb + (r0w + lrow) * QSTR;
        #pragma unroll
        for (int ks = 0; ks < 8; ks++)
            ldsm_x4(qa[ks], qrb + (ks * 2 + lhi) * 16);
    }

    float o[16][4];
    #pragma unroll
    for (int nt = 0; nt < 16; nt++)
        #pragma unroll
        for (int j = 0; j < 4; j++) o[nt][j] = 0.0f;
    float m0s = -1e30f, m1s = -1e30f, l0 = 0.0f, l1 = 0.0f;

    const float sc2 = 0.08838834764831845f * 1.4426950408889634f;
    const int grow0 = q0 + r0w + g;
    const int grow1 = grow0 + 8;

    for (int kt = ktlo; kt <= kthi; ++kt) {
        const int p = (kt - ktlo) & 1;
        const uint32_t kbase  = sb + (p ? AK1b : AK0b);
        const uint32_t vtbase = sb + (p ? AVT1b : AVT0b);

        if (kt < kthi) {
            cpa64(p ? AK0b : AK1b, kg + (size_t)(kt + 1) * 64 * HH);
            CP_COMMIT();
            cpa_vt(p ? AVT0b : AVT1b, kt + 1);
            CP_COMMIT();
            CP_WAIT2();
        } else {
            CP_WAIT0();
        }
        __syncthreads();

        // ---- S = Q K^T ----
        float sa[8][4];
        #pragma unroll
        for (int nt = 0; nt < 8; nt++)
            #pragma unroll
            for (int j = 0; j < 4; j++) sa[nt][j] = 0.0f;

        #pragma unroll
        for (int ks = 0; ks < 8; ks++) {
            const uint32_t choff = (ks * 2 + lhi) * 16;
            #pragma unroll
            for (int nt2 = 0; nt2 < 4; nt2++) {
                uint32_t kb[4];
                ldsm_x4(kb, kbase + (nt2 * 16 + lrow) * QSTR + choff);
                mma_f16(sa[2 * nt2],     qa[ks], kb[0], kb[2]);
                mma_f16(sa[2 * nt2 + 1], qa[ks], kb[1], kb[3]);
            }
        }

        // scale (log2 units) + causal mask on the diagonal tile
        const int k0 = kt * 64;
        #pragma unroll
        for (int nt = 0; nt < 8; nt++)
            #pragma unroll
            for (int j = 0; j < 4; j++) sa[nt][j] *= sc2;
        if (kt == qt) {
            #pragma unroll
            for (int nt = 0; nt < 8; nt++) {
                int colb = k0 + nt * 8 + 2 * c;
                if (colb     > grow0) sa[nt][0] = -1e30f;
                if (colb + 1 > grow0) sa[nt][1] = -1e30f;
                if (colb     > grow1) sa[nt][2] = -1e30f;
                if (colb + 1 > grow1) sa[nt][3] = -1e30f;
            }
        }

        // online softmax (base-2)
        float mt0 = -1e30f, mt1 = -1e30f;
        #pragma unroll
        for (int nt = 0; nt < 8; nt++) {
            mt0 = fmaxf(mt0, fmaxf(sa[nt][0], sa[nt][1]));
            mt1 = fmaxf(mt1, fmaxf(sa[nt][2], sa[nt][3]));
        }
        mt0 = fmaxf(mt0, __shfl_xor_sync(0xffffffffu, mt0, 1));
        mt0 = fmaxf(mt0, __shfl_xor_sync(0xffffffffu, mt0, 2));
        mt1 = fmaxf(mt1, __shfl_xor_sync(0xffffffffu, mt1, 1));
        mt1 = fmaxf(mt1, __shfl_xor_sync(0xffffffffu, mt1, 2));

        const float mn0 = fmaxf(m0s, mt0);
        const float mn1 = fmaxf(m1s, mt1);
        const float al0 = exp2f(m0s - mn0);
        const float al1 = exp2f(m1s - mn1);
        m0s = mn0; m1s = mn1;

        float lt0 = 0.0f, lt1 = 0.0f;
        #pragma unroll
        for (int nt = 0; nt < 8; nt++) {
            sa[nt][0] = exp2f(sa[nt][0] - mn0);
            sa[nt][1] = exp2f(sa[nt][1] - mn0);
            sa[nt][2] = exp2f(sa[nt][2] - mn1);
            sa[nt][3] = exp2f(sa[nt][3] - mn1);
            lt0 += sa[nt][0] + sa[nt][1];
            lt1 += sa[nt][2] + sa[nt][3];
        }
        lt0 += __shfl_xor_sync(0xffffffffu, lt0, 1);
        lt0 += __shfl_xor_sync(0xffffffffu, lt0, 2);
        lt1 += __shfl_xor_sync(0xffffffffu, lt1, 1);
        lt1 += __shfl_xor_sync(0xffffffffu, lt1, 2);
        l0 = l0 * al0 + lt0;
        l1 = l1 * al1 + lt1;

        #pragma unroll
        for (int nt = 0; nt < 16; nt++) {
            o[nt][0] *= al0; o[nt][1] *= al0;
            o[nt][2] *= al1; o[nt][3] *= al1;
        }

        // P -> smem fp16 (warp-private rows, padded 144B rows)
        {
            char* pr0 = smc + APb + (r0w + g) * VSTR + c * 4;
            char* pr8 = pr0 + 8 * VSTR;
            #pragma unroll
            for (int nt = 0; nt < 8; nt++) {
                *reinterpret_cast<uint32_t*>(pr0 + nt * 16) = h2u(sa[nt][0], sa[nt][1]);
                *reinterpret_cast<uint32_t*>(pr8 + nt * 16) = h2u(sa[nt][2], sa[nt][3]);
            }
        }
        __syncwarp();

        // ---- O += P V ----
        #pragma unroll
        for (int ks2 = 0; ks2 < 4; ks2++) {
            const uint32_t choff = (ks2 * 2 + lhi) * 16;
            uint32_t pa[4];
            ldsm_x4(pa, sb + APb + (r0w + lrow) * VSTR + choff);
            #pragma unroll
            for (int ntv = 0; ntv < 8; ntv++) {
                uint32_t vb[4];
                ldsm_x4(vb, vtbase + (ntv * 16 + lrow) * VSTR + choff);
                mma_f16(o[2 * ntv],     pa, vb[0], vb[2]);
                mma_f16(o[2 * ntv + 1], pa, vb[1], vb[3]);
            }
        }
        __syncthreads();
    }

    const int lr0 = r0w + g;          // local row 0..63
    const int lr1 = lr0 + 8;

    if (!partial) {
        const float inv0 = 1.0f / l0;
        const float inv1 = 1.0f / l1;
        #pragma unroll
        for (int nt = 0; nt < 16; nt++) {
            int col = nt * 8 + 2 * c;
            float2 v0 = make_float2(o[nt][0] * inv0, o[nt][1] * inv0);
            float2 v1 = make_float2(o[nt][2] * inv1, o[nt][3] * inv1);
            *reinterpret_cast<float2*>(&out[((size_t)b * TT + grow0) * HH + col]) = v0;
            *reinterpret_cast<float2*>(&out[((size_t)b * TT + grow1) * HH + col]) = v1;
        }
    } else {
        if (c == 0) {
            g_pm[b][qh][split][lr0] = m0s;
            g_pl[b][qh][split][lr0] = l0;
            g_pm[b][qh][split][lr1] = m1s;
            g_pl[b][qh][split][lr1] = l1;
        }
        #pragma unroll
        for (int nt = 0; nt < 16; nt++) {
            int col = nt * 8 + 2 * c;
            *reinterpret_cast<float2*>(&g_po[b][qh][split][lr0][col]) =
                make_float2(o[nt][0], o[nt][1]);
            *reinterpret_cast<float2*>(&g_po[b][qh][split][lr1][col]) =
                make_float2(o[nt][2], o[nt][3]);
        }
    }
}

// ===========================================================================
// Kernel 3: combine split-KV partials for heavy q-tiles.  grid (16, 8).
// ===========================================================================
__global__ __launch_bounds__(256) void attn_combine(float* __restrict__ out)
{
    const int b = blockIdx.y;
    const int qh = blockIdx.x;
    const int qt = 16 + qh;
    const int t = threadIdx.x;
    const int colb = (t & 31) * 4;
    const int rbase = t >> 5;

    #pragma unroll
    for (int pass = 0; pass < 8; pass++) {
        const int row = pass * 8 + rbase;
        const float m0 = g_pm[b][qh][0][row];
        const float m1 = g_pm[b][qh][1][row];
        const float m = fmaxf(m0, m1);
        const float a0 = exp2f(m0 - m);
        const float a1 = exp2f(m1 - m);
        const float invl = 1.0f / (g_pl[b][qh][0][row] * a0 + g_pl[b][qh][1][row] * a1);
        const float4 O0 = *reinterpret_cast<const float4*>(&g_po[b][qh][0][row][colb]);
        const float4 O1 = *reinterpret_cast<const float4*>(&g_po[b][qh][1][row][colb]);
        float4 r;
        r.x = (O0.x * a0 + O1.x * a1) * invl;
        r.y = (O0.y * a0 + O1.y * a1) * invl;
        r.z = (O0.z * a0 + O1.z * a1) * invl;
        r.w = (O0.w * a0 + O1.w * a1) * invl;
        *reinterpret_cast<float4*>(
            &out[((size_t)b * TT + qt * 64 + row) * HH + colb]) = r;
    }
}

// ---------------------------------------------------------------------------
extern "C" void kernel_launch(void* const* d_in, const int* in_sizes, int n_in,
                              void* d_out, int out_size)
{
    const float* x  = (const float*)d_in[0];
    const float* Wq = (const float*)d_in[1];
    const float* Wk = (const float*)d_in[2];
    const float* Wv = (const float*)d_in[3];
    float* out = (float*)d_out;

    cudaFuncSetAttribute(qkv_mma_kernel, cudaFuncAttributeMaxDynamicSharedMemorySize,
                         QKV_SMEM_BYTES);
    cudaFuncSetAttribute(attn_mma_kernel, cudaFuncAttributeMaxDynamicSharedMemorySize,
                         ATT_SMEM_BYTES);

    conv_f2h<<<(BB * TT * CC / 8 + 255) / 256, 256>>>((const float4*)x, 0, BB * TT * CC / 8);
    conv_f2h<<<(HH * CC / 8 + 255) / 256, 256>>>((const float4*)Wq, 1, HH * CC / 8);
    conv_f2h<<<(HH * CC / 8 + 255) / 256, 256>>>((const float4*)Wk, 2, HH * CC / 8);
    conv_f2h<<<(HH * CC / 8 + 255) / 256, 256>>>((const float4*)Wv, 3, HH * CC / 8);

    dim3 g1((BB * TT) / 128, 3);
    qkv_mma_kernel<<<g1, 256, QKV_SMEM_BYTES>>>();

    dim3 g2(48, BB);
    attn_mma_kernel<<<g2, 128, ATT_SMEM_BYTES>>>(out);

    dim3 g3(16, BB);
    attn_combine<<<g3, 256>>>(out);
}